// round 15
// baseline (speedup 1.0000x reference)
#include <cuda_runtime.h>
#include <cuda_fp16.h>
#include <math.h>
#include <stdint.h>

#define BB 2
#define SS 2048
#define HH 4096
#define NH 32
#define NKV 8
#define HD 128

#define NQKV (NH * HD + 2 * NKV * HD)   // 6144 fused output cols

// Scratch (allocation-free rule: __device__ globals)
__device__ __half g_hs[(size_t)BB*SS*HH];         // fp16 hidden
__device__ float  g_q[(size_t)BB*SS*NH*HD];       // f32 q (pre-RoPE)
__device__ float  g_k[(size_t)BB*SS*NKV*HD];
__device__ float  g_v[(size_t)BB*SS*NKV*HD];
__device__ __half g_qh[(size_t)BB*SS*NH*HD];      // fp16 q post-RoPE (pre-scaled)
__device__ __half g_kh[(size_t)BB*SS*NKV*HD];     // fp16 k post-RoPE
__device__ __half g_vT[(size_t)BB*NKV*HD*SS];     // fp16 V transposed [b,hk,d,s]
__device__ __half g_attn[(size_t)BB*SS*NH*HD];    // fp16 attn (O-proj input)
__device__ __half g_wT[(size_t)NQKV*HH];          // fused [6144][4096] K-major fp16
__device__ __half g_woT[(size_t)HH*NH*HD];        // [4096][4096] K-major fp16

// ---------------------------------------------------------------------------
// helpers
// ---------------------------------------------------------------------------
__device__ __forceinline__ uint32_t smem_u32(const void* p) {
    uint32_t a;
    asm("{ .reg .u64 t; cvta.to.shared.u64 t, %1; cvt.u32.u64 %0, t; }"
        : "=r"(a) : "l"(p));
    return a;
}

__device__ __forceinline__ void mma_f16(float* d, const uint32_t* a, const uint32_t* b) {
    asm volatile(
        "mma.sync.aligned.m16n8k16.row.col.f32.f16.f16.f32 "
        "{%0,%1,%2,%3}, {%4,%5,%6,%7}, {%8,%9}, {%0,%1,%2,%3};"
        : "+f"(d[0]), "+f"(d[1]), "+f"(d[2]), "+f"(d[3])
        : "r"(a[0]), "r"(a[1]), "r"(a[2]), "r"(a[3]),
          "r"(b[0]), "r"(b[1]));
}

__device__ __forceinline__ void ldsm_x4(uint32_t* r, uint32_t addr) {
    asm volatile("ldmatrix.sync.aligned.m8n8.x4.shared.b16 {%0,%1,%2,%3}, [%4];"
        : "=r"(r[0]), "=r"(r[1]), "=r"(r[2]), "=r"(r[3]) : "r"(addr));
}

#define CP_ASYNC16(dst, src) \
    asm volatile("cp.async.cg.shared.global [%0], [%1], 16;" \
        :: "r"(dst), "l"(src) : "memory")
#define CP_COMMIT() asm volatile("cp.async.commit_group;" ::: "memory")
#define CP_WAIT1()  asm volatile("cp.async.wait_group 1;" ::: "memory")
#define CP_WAIT0()  asm volatile("cp.async.wait_group 0;" ::: "memory")

// ---------------------------------------------------------------------------
// FP16 HMMA GEMM, cp.async 3-stage pipeline, ldmatrix fragment loads.
// Trailing per-chunk barrier removed: with 3 stages the leading barrier
// (after wait_group 1) already orders chunk i-1 reads before stage reuse.
// ---------------------------------------------------------------------------
#define TBM 128
#define TBN 128
#define TBK 64
#define NSTG 3
#define OPND_B (TBM * TBK * 2)
#define STAGE_B (2 * OPND_B)
#define GEMM_SMEM (NSTG * STAGE_B)

__global__ __launch_bounds__(256, 2) void gemm_f16p(
        const __half* __restrict__ A, const __half* __restrict__ BT,
        float* __restrict__ C0, float* __restrict__ C1, float* __restrict__ C2,
        int M, int N, int K, int n1, int n2, int ns0, int ns1, int ns2) {
    extern __shared__ char smem[];
    uint32_t sb = smem_u32(smem);

    int tid  = threadIdx.x;
    int lane = tid & 31;
    int w    = tid >> 5;
    int wm   = w & 1;
    int wn   = w >> 1;
    int g    = lane >> 2;
    int tg   = lane & 3;

    int bm = blockIdx.y * TBM, bn = blockIdx.x * TBN;

    int l7  = lane & 7;
    int mlo = (lane >> 3) & 1;
    int mhi = lane >> 4;
    int aRowBase = wm * 64 + mlo * 8 + l7;
    int aSegOff  = mhi;
    int bRowBase = wn * 32 + mhi * 8 + l7;
    int bSegOff  = mlo;

    float acc[4][4][4];
#pragma unroll
    for (int i = 0; i < 4; i++)
#pragma unroll
        for (int j = 0; j < 4; j++)
#pragma unroll
            for (int r = 0; r < 4; r++) acc[i][j][r] = 0.f;

    const int NC = K / TBK;

    auto load_chunk = [&](int i, int s) {
        int k0 = i * TBK;
        uint32_t stA = sb + s * STAGE_B;
        uint32_t stB = stA + OPND_B;
#pragma unroll
        for (int j = 0; j < 4; j++) {
            int lin = tid + j * 256;
            int r = lin >> 3, sg = lin & 7;
            uint32_t dA = stA + r * 128 + ((sg ^ (r & 7)) << 4);
            CP_ASYNC16(dA, &A[(size_t)(bm + r) * K + k0 + sg * 8]);
            uint32_t dB = stB + r * 128 + ((sg ^ (r & 7)) << 4);
            CP_ASYNC16(dB, &BT[(size_t)(bn + r) * K + k0 + sg * 8]);
        }
    };

    load_chunk(0, 0); CP_COMMIT();
    load_chunk(1, 1); CP_COMMIT();

    for (int i = 0; i < NC; i++) {
        CP_WAIT1();
        __syncthreads();
        if (i + 2 < NC) load_chunk(i + 2, (i + 2) % NSTG);
        CP_COMMIT();

        uint32_t cA = sb + (i % NSTG) * STAGE_B;
        uint32_t cB = cA + OPND_B;
#pragma unroll
        for (int kk = 0; kk < 4; kk++) {
            uint32_t afr[4][4], bfr[2][4];
#pragma unroll
            for (int mi = 0; mi < 4; mi++) {
                int row = aRowBase + mi * 16;
                int seg = kk * 2 + aSegOff;
                ldsm_x4(afr[mi], cA + row * 128 + (((seg ^ (row & 7)) & 7) << 4));
            }
#pragma unroll
            for (int np = 0; np < 2; np++) {
                int row = bRowBase + np * 16;
                int seg = kk * 2 + bSegOff;
                ldsm_x4(bfr[np], cB + row * 128 + (((seg ^ (row & 7)) & 7) << 4));
            }
#pragma unroll
            for (int mi = 0; mi < 4; mi++)
#pragma unroll
                for (int np = 0; np < 2; np++) {
                    mma_f16(acc[mi][2 * np],     afr[mi], &bfr[np][0]);
                    mma_f16(acc[mi][2 * np + 1], afr[mi], &bfr[np][2]);
                }
        }
        // (no trailing barrier: 3-stage ring makes it redundant)
    }

    float* Cp; int ns, coff;
    if (bn < n1)      { Cp = C0; ns = ns0; coff = bn; }
    else if (bn < n2) { Cp = C1; ns = ns1; coff = bn - n1; }
    else              { Cp = C2; ns = ns2; coff = bn - n2; }

#pragma unroll
    for (int mi = 0; mi < 4; mi++) {
#pragma unroll
        for (int ni = 0; ni < 4; ni++) {
            int row = bm + wm * 64 + mi * 16 + g;
            int col = coff + wn * 32 + ni * 8 + 2 * tg;
            float2 lo = {acc[mi][ni][0], acc[mi][ni][1]};
            float2 hi = {acc[mi][ni][2], acc[mi][ni][3]};
            *(float2*)&Cp[(size_t)row * ns + col]       = lo;
            *(float2*)&Cp[(size_t)(row + 8) * ns + col] = hi;
        }
    }
}

// ---------------------------------------------------------------------------
// Preprocessing kernels
// ---------------------------------------------------------------------------
__global__ void transpose_h(const float* __restrict__ in, __half* __restrict__ out,
                            int R, int C) {
    __shared__ float t[32][33];
    int bx = blockIdx.x * 32, by = blockIdx.y * 32;
    int x = bx + threadIdx.x;
#pragma unroll
    for (int j = threadIdx.y; j < 32; j += 8)
        t[j][threadIdx.x] = in[(size_t)(by + j) * C + x];
    __syncthreads();
    int ox = by + threadIdx.x;
#pragma unroll
    for (int j = threadIdx.y; j < 32; j += 8)
        out[(size_t)(bx + j) * R + ox] = __float2half_rn(t[threadIdx.x][j]);
}

__global__ void f2h_copy(const float* __restrict__ in, __half* __restrict__ out, int n8) {
    int i = blockIdx.x * 256 + threadIdx.x;
    if (i >= n8) return;
    float4 v0 = ((const float4*)in)[2 * i];
    float4 v1 = ((const float4*)in)[2 * i + 1];
    __half2* o = (__half2*)out + 4 * (size_t)i;
    o[0] = __floats2half2_rn(v0.x, v0.y);
    o[1] = __floats2half2_rn(v0.z, v0.w);
    o[2] = __floats2half2_rn(v1.x, v1.y);
    o[3] = __floats2half2_rn(v1.z, v1.w);
}

// V transpose: in g_v [b][s][hk][d] f32 -> out g_vT [b][hk][d][s] fp16
__global__ void v_transpose(const float* __restrict__ in, __half* __restrict__ out) {
    __shared__ float t[32][33];
    int s0 = blockIdx.x * 32, d0 = blockIdx.y * 32;
    int bhk = blockIdx.z;
    int b = bhk / NKV, hk = bhk % NKV;
#pragma unroll
    for (int j = threadIdx.y; j < 32; j += 8)
        t[j][threadIdx.x] =
            in[(((size_t)b * SS + s0 + j) * NKV + hk) * HD + d0 + threadIdx.x];
    __syncthreads();
#pragma unroll
    for (int j = threadIdx.y; j < 32; j += 8)
        out[(((size_t)b * NKV + hk) * HD + d0 + j) * SS + s0 + threadIdx.x] =
            __float2half_rn(t[threadIdx.x][j]);
}

__global__ void rope_h(const float* __restrict__ x, __half* __restrict__ out,
                       const float* __restrict__ cos_t, const float* __restrict__ sin_t,
                       int nheads, float scl, int total) {
    int idx = blockIdx.x * blockDim.x + threadIdx.x;
    if (idx >= total) return;
    int d2 = idx % 32;
    int h  = (idx / 32) % nheads;
    int bs = idx / (32 * nheads);
    int d  = 2 * d2;

    const float* cb = cos_t + (size_t)bs * HD;
    const float* sb = sin_t + (size_t)bs * HD;
    const float* px = x + ((size_t)bs * nheads + h) * HD;
    __half* po = out + ((size_t)bs * nheads + h) * HD;

    float xa0 = px[d],      xa1 = px[d + 1];
    float xb0 = px[d + 64], xb1 = px[d + 65];
    float lo0 = (xa0 * cb[d]      - xb0 * sb[d])      * scl;
    float lo1 = (xa1 * cb[d + 1]  - xb1 * sb[d + 1])  * scl;
    float hi0 = (xb0 * cb[d + 64] + xa0 * sb[d + 64]) * scl;
    float hi1 = (xb1 * cb[d + 65] + xa1 * sb[d + 65]) * scl;
    *(__half2*)(po + d)      = __floats2half2_rn(lo0, lo1);
    *(__half2*)(po + d + 64) = __floats2half2_rn(hi0, hi1);
}

// ---------------------------------------------------------------------------
// Flash attention, fp16 HMMA, ldmatrix frags, cp.async double-buffered K/V.
// BQ=128 per CTA (8 warps x 16 q-rows) -> K/V traffic + per-tile overhead
// halved per unit MMA work. Per-warp math identical to BQ=64 version.
// ---------------------------------------------------------------------------
#define KS_STR 136
#define VS_STR 72
#define TILE_HLV (64 * KS_STR + HD * VS_STR)    // halves per buffer (17920)
#define FLASH_SMEM (2 * TILE_HLV * 2)           // 71680 B
#define BQ 128

__global__ __launch_bounds__(256) void flash_h(const __half* __restrict__ Qh,
                                               const __half* __restrict__ Kh,
                                               const __half* __restrict__ VT,
                                               __half* __restrict__ O) {
    extern __shared__ __half sm[];

    int tid  = threadIdx.x;
    int lane = tid & 31;
    int wid  = tid >> 5;           // 0..7
    int g    = lane >> 2;
    int tg   = lane & 3;
    int l7   = lane & 7;
    int mlo  = (lane >> 3) & 1;
    int mhi  = lane >> 4;

    int qb = blockIdx.x;           // 128-row q block
    int bh = blockIdx.y;
    int b = bh / NH, h = bh % NH;
    int hk = h / (NH / NKV);

    uint32_t smb = smem_u32(sm);
    const __half* kb0 = Kh + ((size_t)b * SS * NKV + hk) * HD;
    const __half* vb0 = VT + (((size_t)b * NKV + hk) * HD) * SS;

    // ---- stage Q tile (128 x 128) flat at smem base, build Q fragments ----
    {
        const __half* qbase = Qh + (((size_t)b * SS + qb * BQ) * NH + h) * HD;
#pragma unroll
        for (int i = 0; i < 8; i++) {
            int c = tid + i * 256;
            int r = c >> 4, in_ = c & 15;
            *(uint4*)&sm[r * KS_STR + in_ * 8] =
                *(const uint4*)(qbase + (size_t)r * NH * HD + in_ * 8);
        }
    }
    __syncthreads();

    uint32_t qf[8][4];
    {
        int rowQ = wid * 16 + mlo * 8 + l7;   // 0..127
#pragma unroll
        for (int kc = 0; kc < 8; kc++)
            ldsm_x4(qf[kc], smb + 2 * (rowQ * KS_STR + kc * 16 + mhi * 8));
    }
    __syncthreads();   // all frags read before cp.async overwrites buffer 0

    // ---- async K/V tile loader into buffer s (256 threads) ----
    auto issue_tile = [&](int kt, int s) {
        uint32_t ksb = smb + 2 * (s * TILE_HLV);
        uint32_t vsb = ksb + 2 * (64 * KS_STR);
        const __half* kb = kb0 + (size_t)(kt * 64) * NKV * HD;
        const __half* vb = vb0 + kt * 64;
#pragma unroll
        for (int i = 0; i < 4; i++) {
            int c = tid + i * 256;
            int r = c >> 4, in_ = c & 15;
            CP_ASYNC16(ksb + 2 * (r * KS_STR + in_ * 8),
                       kb + (size_t)r * NKV * HD + in_ * 8);
        }
#pragma unroll
        for (int i = 0; i < 4; i++) {
            int c = tid + i * 256;
            int r = c >> 3, in_ = c & 7;
            CP_ASYNC16(vsb + 2 * (r * VS_STR + in_ * 8),
                       vb + (size_t)r * SS + in_ * 8);
        }
    };

    float m0 = -1e30f, m1 = -1e30f, l0 = 0.f, l1 = 0.f;
    float o[16][4];
#pragma unroll
    for (int nt = 0; nt < 16; nt++)
#pragma unroll
        for (int r = 0; r < 4; r++) o[nt][r] = 0.f;

    int row0 = qb * BQ + wid * 16 + g;
    int row1 = row0 + 8;

    int bRow = mhi * 8 + l7;   // + np*16
    int bK   = mlo * 8;        // + kc*16

    const int nkt = 2 * qb + 2;   // causal: kv tiles of 64 covering BQ=128 rows

    issue_tile(0, 0); CP_COMMIT();

    for (int kt = 0; kt < nkt; kt++) {
        if (kt < nkt - 1) {
            issue_tile(kt + 1, (kt + 1) & 1);
            CP_COMMIT();
            CP_WAIT1();
        } else {
            CP_WAIT0();
        }
        __syncthreads();

        uint32_t ksb = smb + 2 * ((kt & 1) * TILE_HLV);
        uint32_t vsb = ksb + 2 * (64 * KS_STR);

        // ---- scores S[16][64] per warp (ldmatrix B-frags) ----
        float s[8][4];
#pragma unroll
        for (int nt = 0; nt < 8; nt++)
#pragma unroll
            for (int r = 0; r < 4; r++) s[nt][r] = 0.f;

#pragma unroll
        for (int kc = 0; kc < 8; kc++) {
#pragma unroll
            for (int np = 0; np < 4; np++) {
                uint32_t bf[4];
                ldsm_x4(bf, ksb + 2 * ((np * 16 + bRow) * KS_STR + kc * 16 + bK));
                mma_f16(s[2 * np],     qf[kc], &bf[0]);
                mma_f16(s[2 * np + 1], qf[kc], &bf[2]);
            }
        }

        // ---- causal mask (any tile whose cols can exceed this warp's rows) ----
        if (kt * 64 + 63 > row0) {
#pragma unroll
            for (int nt = 0; nt < 8; nt++) {
                int colb = kt * 64 + nt * 8 + 2 * tg;
#pragma unroll
                for (int e = 0; e < 2; e++) {
                    if (colb + e > row0) s[nt][e]     = -1e30f;
                    if (colb + e > row1) s[nt][2 + e] = -1e30f;
                }
            }
        }

        // ---- online softmax (fp32) ----
        float mx0 = -1e30f, mx1 = -1e30f;
#pragma unroll
        for (int nt = 0; nt < 8; nt++) {
            mx0 = fmaxf(mx0, fmaxf(s[nt][0], s[nt][1]));
            mx1 = fmaxf(mx1, fmaxf(s[nt][2], s[nt][3]));
        }
        mx0 = fmaxf(mx0, __shfl_xor_sync(0xffffffffu, mx0, 1));
        mx0 = fmaxf(mx0, __shfl_xor_sync(0xffffffffu, mx0, 2));
        mx1 = fmaxf(mx1, __shfl_xor_sync(0xffffffffu, mx1, 1));
        mx1 = fmaxf(mx1, __shfl_xor_sync(0xffffffffu, mx1, 2));

        float mn0 = fmaxf(m0, mx0), mn1 = fmaxf(m1, mx1);
        float cr0 = __expf(m0 - mn0), cr1 = __expf(m1 - mn1);
        float lp0 = 0.f, lp1 = 0.f;
#pragma unroll
        for (int nt = 0; nt < 8; nt++) {
            s[nt][0] = __expf(s[nt][0] - mn0);
            s[nt][1] = __expf(s[nt][1] - mn0);
            s[nt][2] = __expf(s[nt][2] - mn1);
            s[nt][3] = __expf(s[nt][3] - mn1);
            lp0 += s[nt][0] + s[nt][1];
            lp1 += s[nt][2] + s[nt][3];
        }
        lp0 += __shfl_xor_sync(0xffffffffu, lp0, 1);
        lp0 += __shfl_xor_sync(0xffffffffu, lp0, 2);
        lp1 += __shfl_xor_sync(0xffffffffu, lp1, 1);
        lp1 += __shfl_xor_sync(0xffffffffu, lp1, 2);
        l0 = l0 * cr0 + lp0;
        l1 = l1 * cr1 + lp1;
        m0 = mn0; m1 = mn1;

#pragma unroll
        for (int nt = 0; nt < 16; nt++) {
            o[nt][0] *= cr0; o[nt][1] *= cr0;
            o[nt][2] *= cr1; o[nt][3] *= cr1;
        }

        // ---- pack P as A-frags ----
        uint32_t pf[4][4];
#pragma unroll
        for (int kc = 0; kc < 4; kc++) {
            int t0 = 2 * kc, t1 = 2 * kc + 1;
            __half2 h00 = __floats2half2_rn(s[t0][0], s[t0][1]);
            __half2 h01 = __floats2half2_rn(s[t0][2], s[t0][3]);
            __half2 h10 = __floats2half2_rn(s[t1][0], s[t1][1]);
            __half2 h11 = __floats2half2_rn(s[t1][2], s[t1][3]);
            pf[kc][0] = *(uint32_t*)&h00;
            pf[kc][1] = *(uint32_t*)&h01;
            pf[kc][2] = *(uint32_t*)&h10;
            pf[kc][3] = *(uint32_t*)&h11;
        }

        // ---- O += P @ V (ldmatrix VT frags) ----
#pragma unroll
        for (int kc = 0; kc < 4; kc++) {
#pragma unroll
            for (int np = 0; np < 8; np++) {
                uint32_t bf[4];
                ldsm_x4(bf, vsb + 2 * ((np * 16 + bRow) * VS_STR + kc * 16 + bK));
                mma_f16(o[2 * np],     pf[kc], &bf[0]);
                mma_f16(o[2 * np + 1], pf[kc], &bf[2]);
            }
        }
        __syncthreads();   // needed: 2-buffer ring
    }

    // ---- epilogue: O /= l, write fp16 ----
    float inv0 = 1.f / l0, inv1 = 1.f / l1;
    __half* ob = O + (((size_t)b * SS) * NH + h) * HD;
#pragma unroll
    for (int nt = 0; nt < 16; nt++) {
        int col = nt * 8 + 2 * tg;
        __half2 v0 = __floats2half2_rn(o[nt][0] * inv0, o[nt][1] * inv0);
        __half2 v1 = __floats2half2_rn(o[nt][2] * inv1, o[nt][3] * inv1);
        *(__half2*)(ob + (size_t)row0 * NH * HD + col) = v0;
        *(__half2*)(ob + (size_t)row1 * NH * HD + col) = v1;
    }
}

// ---------------------------------------------------------------------------
// Launch
// ---------------------------------------------------------------------------
extern "C" void kernel_launch(void* const* d_in, const int* in_sizes, int n_in,
                              void* d_out, int out_size) {
    const float* hidden = (const float*)d_in[0];
    const float* cosv   = (const float*)d_in[1];
    const float* sinv   = (const float*)d_in[2];
    const float* wq     = (const float*)d_in[3];
    const float* wk     = (const float*)d_in[4];
    const float* wv     = (const float*)d_in[5];
    const float* wo     = (const float*)d_in[6];
    float* out = (float*)d_out;

    void *phs, *pq, *pk, *pv, *pqh, *pkh, *pvT, *pattn, *pwT, *pwo;
    cudaGetSymbolAddress(&phs, g_hs);
    cudaGetSymbolAddress(&pq, g_q);
    cudaGetSymbolAddress(&pk, g_k);
    cudaGetSymbolAddress(&pv, g_v);
    cudaGetSymbolAddress(&pqh, g_qh);
    cudaGetSymbolAddress(&pkh, g_kh);
    cudaGetSymbolAddress(&pvT, g_vT);
    cudaGetSymbolAddress(&pattn, g_attn);
    cudaGetSymbolAddress(&pwT, g_wT);
    cudaGetSymbolAddress(&pwo, g_woT);
    __half* dhs = (__half*)phs;
    float* dq = (float*)pq;
    float* dk = (float*)pk;
    float* dv = (float*)pv;
    __half* dqh = (__half*)pqh;
    __half* dkh = (__half*)pkh;
    __half* dvT = (__half*)pvT;
    __half* dattn = (__half*)pattn;
    __half* dwT = (__half*)pwT;
    __half* dwoT = (__half*)pwo;

    cudaFuncSetAttribute(gemm_f16p, cudaFuncAttributeMaxDynamicSharedMemorySize,
                         GEMM_SMEM);
    cudaFuncSetAttribute(flash_h, cudaFuncAttributeMaxDynamicSharedMemorySize,
                         FLASH_SMEM);

    const int M  = BB * SS;       // 4096
    const int NQ = NH * HD;       // 4096
    const int NK = NKV * HD;      // 1024

    // preprocessing
    int n8 = BB * SS * HH / 8;
    f2h_copy<<<(n8 + 255) / 256, 256>>>(hidden, dhs, n8);
    transpose_h<<<dim3(NQ / 32, HH / 32), dim3(32, 8)>>>(wq, dwT, HH, NQ);
    transpose_h<<<dim3(NK / 32, HH / 32), dim3(32, 8)>>>(wk, dwT + (size_t)NQ * HH, HH, NK);
    transpose_h<<<dim3(NK / 32, HH / 32), dim3(32, 8)>>>(wv, dwT + (size_t)(NQ + NK) * HH, HH, NK);
    transpose_h<<<dim3(HH / 32, NQ / 32), dim3(32, 8)>>>(wo, dwoT, NQ, HH);

    // fused QKV projection
    gemm_f16p<<<dim3(NQKV / TBN, M / TBM), 256, GEMM_SMEM>>>(
        dhs, dwT, dq, dk, dv, M, NQKV, HH, NQ, NQ + NK, NQ, NK, NK);

    // RoPE -> fp16 (q pre-scaled by 1/sqrt(HD))
    const float scl = 1.f / sqrtf((float)HD);
    int tq = BB * SS * NH * 32;
    rope_h<<<(tq + 255) / 256, 256>>>(dq, dqh, cosv, sinv, NH, scl, tq);
    int tk = BB * SS * NKV * 32;
    rope_h<<<(tk + 255) / 256, 256>>>(dk, dkh, cosv, sinv, NKV, 1.f, tk);

    // V transpose to [b,hk,d,s] fp16
    v_transpose<<<dim3(SS / 32, HD / 32, BB * NKV), dim3(32, 8)>>>(dv, dvT);

    // Flash attention (fp16 HMMA, BQ=128, double-buffered cp.async)
    flash_h<<<dim3(SS / BQ, BB * NH), 256, FLASH_SMEM>>>(dqh, dkh, dvT, dattn);

    // Output projection
    gemm_f16p<<<dim3(HH / TBN, M / TBM), 256, GEMM_SMEM>>>(
        dattn, dwoT, out, out, out, M, HH, NQ, HH, HH, HH, HH, HH);
}